// round 1
// baseline (speedup 1.0000x reference)
#include <cuda_runtime.h>
#include <cstdint>
#include <math.h>

#define T_TOK 8192
#define DIM   1024
#define MLPD  2048
#define NEXP  8

#define BM 128
#define BN 128
#define BK 16
#define APAD 20
#define BPAD 132

// ---------------- scratch (static device globals; no allocation) ------------
__device__ int   g_count[NEXP];
__device__ int   g_tok [NEXP * T_TOK];
__device__ int   g_slot[NEXP * T_TOK];
__device__ float g_coef[NEXP * T_TOK];
__device__ float g_h   [(size_t)NEXP * T_TOK * MLPD];   // SwiGLU intermediate
__device__ float g_out2[2ull * T_TOK * DIM];            // per-slot combine buffers

// ---------------- helpers ---------------------------------------------------
__device__ __forceinline__ uint32_t f2tf(float f) {
    uint32_t u;
    asm("cvt.rna.tf32.f32 %0, %1;" : "=r"(u) : "f"(f));
    return u;
}

__device__ __forceinline__ void mma8(float c[4], const uint32_t a[4], const uint32_t b[2]) {
    asm volatile(
        "mma.sync.aligned.m16n8k8.row.col.f32.tf32.tf32.f32 "
        "{%0,%1,%2,%3}, {%4,%5,%6,%7}, {%8,%9}, {%0,%1,%2,%3};"
        : "+f"(c[0]), "+f"(c[1]), "+f"(c[2]), "+f"(c[3])
        : "r"(a[0]), "r"(a[1]), "r"(a[2]), "r"(a[3]), "r"(b[0]), "r"(b[1]));
}

// ---------------- kernel 0: zero counters -----------------------------------
__global__ void k_zero() {
    if (threadIdx.x < NEXP) g_count[threadIdx.x] = 0;
}

// ---------------- kernel 1: router (one warp per token) ---------------------
__global__ void k_router(const float* __restrict__ x, const float* __restrict__ gw) {
    int gtid = blockIdx.x * blockDim.x + threadIdx.x;
    int wid  = gtid >> 5;
    int lane = gtid & 31;
    if (wid >= T_TOK) return;

    const float* xr = x + (size_t)wid * DIM;
    float acc[8] = {0.f, 0.f, 0.f, 0.f, 0.f, 0.f, 0.f, 0.f};
    for (int d = lane; d < DIM; d += 32) {
        float xv = __ldg(xr + d);
        const float4 g0 = *(const float4*)(gw + d * 8);
        const float4 g1 = *(const float4*)(gw + d * 8 + 4);
        acc[0] += xv * g0.x; acc[1] += xv * g0.y; acc[2] += xv * g0.z; acc[3] += xv * g0.w;
        acc[4] += xv * g1.x; acc[5] += xv * g1.y; acc[6] += xv * g1.z; acc[7] += xv * g1.w;
    }
#pragma unroll
    for (int i = 0; i < 8; i++) {
#pragma unroll
        for (int o = 16; o; o >>= 1) acc[i] += __shfl_xor_sync(0xffffffffu, acc[i], o);
    }
    if (lane == 0) {
        // top-2 of logits == top-2 of softmax; renormalized weights: the full
        // softmax denominator cancels, so only the two exps are needed.
        int e0 = 0;
#pragma unroll
        for (int i = 1; i < 8; i++) if (acc[i] > acc[e0]) e0 = i;
        int e1 = -1;
#pragma unroll
        for (int i = 0; i < 8; i++) {
            if (i == e0) continue;
            if (e1 < 0 || acc[i] > acc[e1]) e1 = i;
        }
        float m  = acc[e0];
        float p0 = expf(acc[e0] - m);
        float p1 = expf(acc[e1] - m);
        float s  = p0 + p1;
        float w0 = p0 / s, w1 = p1 / s;

        int pos0 = atomicAdd(&g_count[e0], 1);
        g_tok [e0 * T_TOK + pos0] = wid;
        g_slot[e0 * T_TOK + pos0] = 0;
        g_coef[e0 * T_TOK + pos0] = w0;
        int pos1 = atomicAdd(&g_count[e1], 1);
        g_tok [e1 * T_TOK + pos1] = wid;
        g_slot[e1 * T_TOK + pos1] = 1;
        g_coef[e1 * T_TOK + pos1] = w1;
    }
}

// ---------------- kernel 2: GEMM1 (x·w1, x·w3) + SwiGLU ---------------------
// grid: (MLPD/BN, T_TOK/BM, NEXP); 256 threads = 8 warps (4 M x 2 N), warp tile 32x64
__global__ __launch_bounds__(256, 1)
void k_gemm1(const float* __restrict__ x,
             const float* __restrict__ w1,
             const float* __restrict__ w3) {
    int e   = blockIdx.z;
    int cnt = g_count[e];
    int mt  = blockIdx.y;
    if (mt * BM >= cnt) return;
    int nt  = blockIdx.x;

    __shared__ uint32_t As [BM * APAD];
    __shared__ uint32_t B1s[BK * BPAD];
    __shared__ uint32_t B3s[BK * BPAD];
    __shared__ int      sTok[BM];

    int tid    = threadIdx.x;
    int warpId = tid >> 5;
    int lane   = tid & 31;
    int gid    = lane >> 2;
    int tig    = lane & 3;
    int mBase  = (warpId & 3) * 32;
    int nBase  = (warpId >> 2) * 64;

    if (tid < BM) {
        int r = mt * BM + tid;
        sTok[tid] = (r < cnt) ? g_tok[e * T_TOK + r] : g_tok[e * T_TOK];
    }

    float c1[2][8][4], c3[2][8][4];
#pragma unroll
    for (int a = 0; a < 2; a++)
#pragma unroll
        for (int b = 0; b < 8; b++)
#pragma unroll
            for (int d = 0; d < 4; d++) { c1[a][b][d] = 0.f; c3[a][b][d] = 0.f; }

    const float* w1p = w1 + (size_t)e * DIM * MLPD;
    const float* w3p = w3 + (size_t)e * DIM * MLPD;

    for (int k0 = 0; k0 < DIM; k0 += BK) {
        __syncthreads();
        // A tile: 128 rows x 16 cols (gathered token rows), 512 float4s
#pragma unroll
        for (int i = 0; i < 2; i++) {
            int q  = tid + i * 256;
            int r  = q >> 2;
            int c4 = (q & 3) * 4;
            const float4 v = *(const float4*)(x + (size_t)sTok[r] * DIM + k0 + c4);
            uint32_t* dst = As + r * APAD + c4;
            dst[0] = f2tf(v.x); dst[1] = f2tf(v.y); dst[2] = f2tf(v.z); dst[3] = f2tf(v.w);
        }
        // B tiles: 16 rows x 128 cols each
#pragma unroll
        for (int i = 0; i < 2; i++) {
            int q  = tid + i * 256;
            int r  = q >> 5;
            int c4 = (q & 31) * 4;
            size_t off = (size_t)(k0 + r) * MLPD + nt * BN + c4;
            const float4 v1 = *(const float4*)(w1p + off);
            const float4 v3 = *(const float4*)(w3p + off);
            uint32_t* d1 = B1s + r * BPAD + c4;
            d1[0] = f2tf(v1.x); d1[1] = f2tf(v1.y); d1[2] = f2tf(v1.z); d1[3] = f2tf(v1.w);
            uint32_t* d3 = B3s + r * BPAD + c4;
            d3[0] = f2tf(v3.x); d3[1] = f2tf(v3.y); d3[2] = f2tf(v3.z); d3[3] = f2tf(v3.w);
        }
        __syncthreads();

#pragma unroll
        for (int kk = 0; kk < BK; kk += 8) {
            uint32_t a[2][4];
#pragma unroll
            for (int ms = 0; ms < 2; ms++) {
                int rb = mBase + ms * 16;
                a[ms][0] = As[(rb + gid    ) * APAD + kk + tig    ];
                a[ms][1] = As[(rb + gid + 8) * APAD + kk + tig    ];
                a[ms][2] = As[(rb + gid    ) * APAD + kk + tig + 4];
                a[ms][3] = As[(rb + gid + 8) * APAD + kk + tig + 4];
            }
#pragma unroll
            for (int ns = 0; ns < 8; ns++) {
                int ncol = nBase + ns * 8 + gid;
                uint32_t b1f[2] = { B1s[(kk + tig) * BPAD + ncol], B1s[(kk + tig + 4) * BPAD + ncol] };
                uint32_t b3f[2] = { B3s[(kk + tig) * BPAD + ncol], B3s[(kk + tig + 4) * BPAD + ncol] };
                mma8(c1[0][ns], a[0], b1f);
                mma8(c1[1][ns], a[1], b1f);
                mma8(c3[0][ns], a[0], b3f);
                mma8(c3[1][ns], a[1], b3f);
            }
        }
    }

    // SwiGLU epilogue -> g_h
#pragma unroll
    for (int ms = 0; ms < 2; ms++) {
#pragma unroll
        for (int half = 0; half < 2; half++) {
            int grow = mt * BM + mBase + ms * 16 + gid + half * 8;
            if (grow < cnt) {
                size_t rowoff = ((size_t)e * T_TOK + grow) * MLPD;
#pragma unroll
                for (int ns = 0; ns < 8; ns++) {
                    int col = nt * BN + nBase + ns * 8 + tig * 2;
                    float v1a = c1[ms][ns][half * 2 + 0];
                    float v1b = c1[ms][ns][half * 2 + 1];
                    float v3a = c3[ms][ns][half * 2 + 0];
                    float v3b = c3[ms][ns][half * 2 + 1];
                    g_h[rowoff + col    ] = v1a / (1.f + expf(-v1a)) * v3a;
                    g_h[rowoff + col + 1] = v1b / (1.f + expf(-v1b)) * v3b;
                }
            }
        }
    }
}

// ---------------- kernel 3: GEMM2 (h·w2, scaled) ----------------------------
// grid: (DIM/BN, T_TOK/BM, NEXP)
__global__ __launch_bounds__(256, 1)
void k_gemm2(const float* __restrict__ w2) {
    int e   = blockIdx.z;
    int cnt = g_count[e];
    int mt  = blockIdx.y;
    if (mt * BM >= cnt) return;
    int nt  = blockIdx.x;

    __shared__ uint32_t As[BM * APAD];
    __shared__ uint32_t Bs[BK * BPAD];

    int tid    = threadIdx.x;
    int warpId = tid >> 5;
    int lane   = tid & 31;
    int gid    = lane >> 2;
    int tig    = lane & 3;
    int mBase  = (warpId & 3) * 32;
    int nBase  = (warpId >> 2) * 64;

    float c[2][8][4];
#pragma unroll
    for (int a = 0; a < 2; a++)
#pragma unroll
        for (int b = 0; b < 8; b++)
#pragma unroll
            for (int d = 0; d < 4; d++) c[a][b][d] = 0.f;

    const float* w2p   = w2 + (size_t)e * MLPD * DIM;
    const float* hrows = g_h + ((size_t)e * T_TOK + (size_t)mt * BM) * MLPD;

    for (int k0 = 0; k0 < MLPD; k0 += BK) {
        __syncthreads();
#pragma unroll
        for (int i = 0; i < 2; i++) {
            int q  = tid + i * 256;
            int r  = q >> 2;
            int c4 = (q & 3) * 4;
            // rows past cnt read stale scratch (in-bounds); results discarded.
            const float4 v = *(const float4*)(hrows + (size_t)r * MLPD + k0 + c4);
            uint32_t* dst = As + r * APAD + c4;
            dst[0] = f2tf(v.x); dst[1] = f2tf(v.y); dst[2] = f2tf(v.z); dst[3] = f2tf(v.w);
        }
#pragma unroll
        for (int i = 0; i < 2; i++) {
            int q  = tid + i * 256;
            int r  = q >> 5;
            int c4 = (q & 31) * 4;
            const float4 v = *(const float4*)(w2p + (size_t)(k0 + r) * DIM + nt * BN + c4);
            uint32_t* d1 = Bs + r * BPAD + c4;
            d1[0] = f2tf(v.x); d1[1] = f2tf(v.y); d1[2] = f2tf(v.z); d1[3] = f2tf(v.w);
        }
        __syncthreads();

#pragma unroll
        for (int kk = 0; kk < BK; kk += 8) {
            uint32_t a[2][4];
#pragma unroll
            for (int ms = 0; ms < 2; ms++) {
                int rb = mBase + ms * 16;
                a[ms][0] = As[(rb + gid    ) * APAD + kk + tig    ];
                a[ms][1] = As[(rb + gid + 8) * APAD + kk + tig    ];
                a[ms][2] = As[(rb + gid    ) * APAD + kk + tig + 4];
                a[ms][3] = As[(rb + gid + 8) * APAD + kk + tig + 4];
            }
#pragma unroll
            for (int ns = 0; ns < 8; ns++) {
                int ncol = nBase + ns * 8 + gid;
                uint32_t bf[2] = { Bs[(kk + tig) * BPAD + ncol], Bs[(kk + tig + 4) * BPAD + ncol] };
                mma8(c[0][ns], a[0], bf);
                mma8(c[1][ns], a[1], bf);
            }
        }
    }

    // scaled scatter into per-slot buffers (each (slot, token) written once)
#pragma unroll
    for (int ms = 0; ms < 2; ms++) {
#pragma unroll
        for (int half = 0; half < 2; half++) {
            int grow = mt * BM + mBase + ms * 16 + gid + half * 8;
            if (grow < cnt) {
                int   gi = e * T_TOK + grow;
                int   t  = g_tok[gi];
                int   s  = g_slot[gi];
                float cf = g_coef[gi];
                float* op = g_out2 + ((size_t)s * T_TOK + t) * DIM + nt * BN + nBase;
#pragma unroll
                for (int ns = 0; ns < 8; ns++) {
                    int col = ns * 8 + tig * 2;
                    op[col    ] = cf * c[ms][ns][half * 2 + 0];
                    op[col + 1] = cf * c[ms][ns][half * 2 + 1];
                }
            }
        }
    }
}

// ---------------- kernel 4: combine slots -> output -------------------------
__global__ void k_combine(float* __restrict__ out) {
    size_t i = ((size_t)blockIdx.x * 256 + threadIdx.x) * 4;
    float4 a = *(const float4*)(g_out2 + i);
    float4 b = *(const float4*)(g_out2 + (size_t)T_TOK * DIM + i);
    float4 r;
    r.x = a.x + b.x; r.y = a.y + b.y; r.z = a.z + b.z; r.w = a.w + b.w;
    *(float4*)(out + i) = r;
}

// ---------------- launch -----------------------------------------------------
extern "C" void kernel_launch(void* const* d_in, const int* in_sizes, int n_in,
                              void* d_out, int out_size) {
    const float* x  = (const float*)d_in[0];
    const float* gw = (const float*)d_in[1];
    const float* w1 = (const float*)d_in[2];
    const float* w2 = (const float*)d_in[3];
    const float* w3 = (const float*)d_in[4];

    k_zero<<<1, 32>>>();
    k_router<<<T_TOK / 8, 256>>>(x, gw);          // 8 warps per block

    dim3 g1(MLPD / BN, T_TOK / BM, NEXP);          // (16, 64, 8)
    k_gemm1<<<g1, 256>>>(x, w1, w3);

    dim3 g2(DIM / BN, T_TOK / BM, NEXP);           // (8, 64, 8)
    k_gemm2<<<g2, 256>>>(w2);

    k_combine<<<(T_TOK * DIM / 4) / 256, 256>>>((float*)d_out);
}

// round 8
// speedup vs baseline: 1.3922x; 1.3922x over previous
#include <cuda_runtime.h>
#include <cstdint>
#include <math.h>

#define T_TOK 8192
#define DIM   1024
#define MLPD  2048
#define NEXP  8

#define BM 128
#define BN 128
#define BK 32
#define APAD 36     // uint32 pitch for A [row][k]  -> frag banks gid*4+tig (conflict-free)
#define BPAD 136    // uint32 pitch for B [k][col]  -> frag banks tig*8+gid (conflict-free)

#define NTHREADS 512

// smem (uint32 words)
#define A_WORDS   (BM * APAD)          // 4608
#define B_WORDS   (BK * BPAD)          // 4352
#define SMEM1_BYTES ((A_WORDS + 2 * B_WORDS) * 4 + BM * 4)   // A + B1 + B3 + sTok = 53760
#define SMEM2_BYTES ((A_WORDS + B_WORDS) * 4)                // 35840

// ---------------- scratch (static device globals; no allocation) ------------
__device__ int   g_count[NEXP];
__device__ int   g_tok [NEXP * T_TOK];
__device__ int   g_slot[NEXP * T_TOK];
__device__ float g_coef[NEXP * T_TOK];
__device__ float g_h   [(size_t)NEXP * T_TOK * MLPD];
__device__ float g_out2[2ull * T_TOK * DIM];

// ---------------- helpers ---------------------------------------------------
__device__ __forceinline__ uint32_t f2tf(float f) {
    uint32_t u;
    asm("cvt.rna.tf32.f32 %0, %1;" : "=r"(u) : "f"(f));
    return u;
}

__device__ __forceinline__ void mma8(float c[4], const uint32_t a[4], const uint32_t b[2]) {
    asm volatile(
        "mma.sync.aligned.m16n8k8.row.col.f32.tf32.tf32.f32 "
        "{%0,%1,%2,%3}, {%4,%5,%6,%7}, {%8,%9}, {%0,%1,%2,%3};"
        : "+f"(c[0]), "+f"(c[1]), "+f"(c[2]), "+f"(c[3])
        : "r"(a[0]), "r"(a[1]), "r"(a[2]), "r"(a[3]), "r"(b[0]), "r"(b[1]));
}

// ---------------- kernel 0: zero counters -----------------------------------
__global__ void k_zero() {
    if (threadIdx.x < NEXP) g_count[threadIdx.x] = 0;
}

// ---------------- kernel 1: router (one warp per token) ---------------------
__global__ void k_router(const float* __restrict__ x, const float* __restrict__ gw) {
    int gtid = blockIdx.x * blockDim.x + threadIdx.x;
    int wid  = gtid >> 5;
    int lane = gtid & 31;
    if (wid >= T_TOK) return;

    const float* xr = x + (size_t)wid * DIM;
    float acc[8] = {0.f, 0.f, 0.f, 0.f, 0.f, 0.f, 0.f, 0.f};
    for (int d = lane; d < DIM; d += 32) {
        float xv = __ldg(xr + d);
        const float4 g0 = *(const float4*)(gw + d * 8);
        const float4 g1 = *(const float4*)(gw + d * 8 + 4);
        acc[0] += xv * g0.x; acc[1] += xv * g0.y; acc[2] += xv * g0.z; acc[3] += xv * g0.w;
        acc[4] += xv * g1.x; acc[5] += xv * g1.y; acc[6] += xv * g1.z; acc[7] += xv * g1.w;
    }
#pragma unroll
    for (int i = 0; i < 8; i++) {
#pragma unroll
        for (int o = 16; o; o >>= 1) acc[i] += __shfl_xor_sync(0xffffffffu, acc[i], o);
    }
    if (lane == 0) {
        int e0 = 0;
#pragma unroll
        for (int i = 1; i < 8; i++) if (acc[i] > acc[e0]) e0 = i;
        int e1 = -1;
#pragma unroll
        for (int i = 0; i < 8; i++) {
            if (i == e0) continue;
            if (e1 < 0 || acc[i] > acc[e1]) e1 = i;
        }
        float m  = acc[e0];
        float p0 = expf(acc[e0] - m);
        float p1 = expf(acc[e1] - m);
        float s  = p0 + p1;

        int pos0 = atomicAdd(&g_count[e0], 1);
        g_tok [e0 * T_TOK + pos0] = wid;
        g_slot[e0 * T_TOK + pos0] = 0;
        g_coef[e0 * T_TOK + pos0] = p0 / s;
        int pos1 = atomicAdd(&g_count[e1], 1);
        g_tok [e1 * T_TOK + pos1] = wid;
        g_slot[e1 * T_TOK + pos1] = 1;
        g_coef[e1 * T_TOK + pos1] = p1 / s;
    }
}

// ---------------- kernel 2: GEMM1 (x·w1, x·w3) + SwiGLU ---------------------
// grid (MLPD/BN, T_TOK/BM, NEXP), 512 threads = 16 warps (4M x 4N), warp tile 32x32
__global__ __launch_bounds__(NTHREADS, 1)
void k_gemm1(const float* __restrict__ x,
             const float* __restrict__ w1,
             const float* __restrict__ w3) {
    int e   = blockIdx.z;
    int cnt = g_count[e];
    int mt  = blockIdx.y;
    if (mt * BM >= cnt) return;
    int nt  = blockIdx.x;

    extern __shared__ uint32_t sm[];
    uint32_t* As  = sm;
    uint32_t* B1s = sm + A_WORDS;
    uint32_t* B3s = sm + A_WORDS + B_WORDS;
    int*      sTok = (int*)(sm + A_WORDS + 2 * B_WORDS);

    int tid    = threadIdx.x;
    int warpId = tid >> 5;
    int lane   = tid & 31;
    int gid    = lane >> 2;
    int tig    = lane & 3;
    int mBase  = (warpId & 3) * 32;
    int nBase  = (warpId >> 2) * 32;

    if (tid < BM) {
        int r = mt * BM + tid;
        sTok[tid] = (r < cnt) ? g_tok[e * T_TOK + r] : g_tok[e * T_TOK];
    }

    float c1[2][4][4], c3[2][4][4];
#pragma unroll
    for (int a = 0; a < 2; a++)
#pragma unroll
        for (int b = 0; b < 4; b++)
#pragma unroll
            for (int d = 0; d < 4; d++) { c1[a][b][d] = 0.f; c3[a][b][d] = 0.f; }

    const float* w1p = w1 + (size_t)e * DIM * MLPD + nt * BN;
    const float* w3p = w3 + (size_t)e * DIM * MLPD + nt * BN;
    __syncthreads();

    for (int k0 = 0; k0 < DIM; k0 += BK) {
        // A tile: 128 x 32 floats (1024 float4s)
#pragma unroll
        for (int i = 0; i < 2; i++) {
            int f  = tid + i * NTHREADS;
            int r  = f >> 3;
            int c4 = (f & 7) * 4;
            const float4 v = *(const float4*)(x + (size_t)sTok[r] * DIM + k0 + c4);
            uint32_t* dst = As + r * APAD + c4;
            dst[0] = f2tf(v.x); dst[1] = f2tf(v.y); dst[2] = f2tf(v.z); dst[3] = f2tf(v.w);
        }
        // B tiles: 32 x 128 floats each (1024 float4s each)
#pragma unroll
        for (int i = 0; i < 2; i++) {
            int f  = tid + i * NTHREADS;
            int r  = f >> 5;
            int c4 = (f & 31) * 4;
            size_t off = (size_t)(k0 + r) * MLPD + c4;
            const float4 v1 = *(const float4*)(w1p + off);
            const float4 v3 = *(const float4*)(w3p + off);
            uint32_t* d1 = B1s + r * BPAD + c4;
            d1[0] = f2tf(v1.x); d1[1] = f2tf(v1.y); d1[2] = f2tf(v1.z); d1[3] = f2tf(v1.w);
            uint32_t* d3 = B3s + r * BPAD + c4;
            d3[0] = f2tf(v3.x); d3[1] = f2tf(v3.y); d3[2] = f2tf(v3.z); d3[3] = f2tf(v3.w);
        }
        __syncthreads();

#pragma unroll
        for (int kk = 0; kk < BK; kk += 8) {
            uint32_t a[2][4];
#pragma unroll
            for (int ms = 0; ms < 2; ms++) {
                int rb = mBase + ms * 16;
                a[ms][0] = As[(rb + gid    ) * APAD + kk + tig    ];
                a[ms][1] = As[(rb + gid + 8) * APAD + kk + tig    ];
                a[ms][2] = As[(rb + gid    ) * APAD + kk + tig + 4];
                a[ms][3] = As[(rb + gid + 8) * APAD + kk + tig + 4];
            }
#pragma unroll
            for (int ns = 0; ns < 4; ns++) {
                int ncol = nBase + ns * 8 + gid;
                uint32_t b1f[2] = { B1s[(kk + tig) * BPAD + ncol], B1s[(kk + tig + 4) * BPAD + ncol] };
                uint32_t b3f[2] = { B3s[(kk + tig) * BPAD + ncol], B3s[(kk + tig + 4) * BPAD + ncol] };
                mma8(c1[0][ns], a[0], b1f);
                mma8(c1[1][ns], a[1], b1f);
                mma8(c3[0][ns], a[0], b3f);
                mma8(c3[1][ns], a[1], b3f);
            }
        }
        __syncthreads();
    }

    // SwiGLU epilogue -> g_h (tf32-rounded, so GEMM2's cvt is exact)
#pragma unroll
    for (int ms = 0; ms < 2; ms++) {
#pragma unroll
        for (int half = 0; half < 2; half++) {
            int grow = mt * BM + mBase + ms * 16 + gid + half * 8;
            if (grow < cnt) {
                size_t rowoff = ((size_t)e * T_TOK + grow) * MLPD;
#pragma unroll
                for (int ns = 0; ns < 4; ns++) {
                    int col = nt * BN + nBase + ns * 8 + tig * 2;
                    float v1a = c1[ms][ns][half * 2 + 0];
                    float v1b = c1[ms][ns][half * 2 + 1];
                    float v3a = c3[ms][ns][half * 2 + 0];
                    float v3b = c3[ms][ns][half * 2 + 1];
                    float2 o;
                    o.x = v1a / (1.f + expf(-v1a)) * v3a;
                    o.y = v1b / (1.f + expf(-v1b)) * v3b;
                    o.x = __uint_as_float(f2tf(o.x));
                    o.y = __uint_as_float(f2tf(o.y));
                    *(float2*)(g_h + rowoff + col) = o;
                }
            }
        }
    }
}

// ---------------- kernel 3: GEMM2 (h·w2, scaled scatter) --------------------
// grid (DIM/BN, T_TOK/BM, NEXP), 512 threads
__global__ __launch_bounds__(NTHREADS, 1)
void k_gemm2(const float* __restrict__ w2) {
    int e   = blockIdx.z;
    int cnt = g_count[e];
    int mt  = blockIdx.y;
    if (mt * BM >= cnt) return;
    int nt  = blockIdx.x;

    __shared__ uint32_t As[A_WORDS];
    __shared__ uint32_t Bs[B_WORDS];

    int tid    = threadIdx.x;
    int warpId = tid >> 5;
    int lane   = tid & 31;
    int gid    = lane >> 2;
    int tig    = lane & 3;
    int mBase  = (warpId & 3) * 32;
    int nBase  = (warpId >> 2) * 32;

    float c[2][4][4];
#pragma unroll
    for (int a = 0; a < 2; a++)
#pragma unroll
        for (int b = 0; b < 4; b++)
#pragma unroll
            for (int d = 0; d < 4; d++) c[a][b][d] = 0.f;

    const float* w2p   = w2 + (size_t)e * MLPD * DIM + nt * BN;
    const float* hrows = g_h + ((size_t)e * T_TOK + (size_t)mt * BM) * MLPD;

    for (int k0 = 0; k0 < MLPD; k0 += BK) {
#pragma unroll
        for (int i = 0; i < 2; i++) {
            int f  = tid + i * NTHREADS;
            int r  = f >> 3;
            int c4 = (f & 7) * 4;
            // h is already tf32-rounded; rows >= cnt are stale-but-finite, discarded.
            const float4 v = *(const float4*)(hrows + (size_t)r * MLPD + k0 + c4);
            uint32_t* dst = As + r * APAD + c4;
            dst[0] = __float_as_uint(v.x); dst[1] = __float_as_uint(v.y);
            dst[2] = __float_as_uint(v.z); dst[3] = __float_as_uint(v.w);
        }
#pragma unroll
        for (int i = 0; i < 2; i++) {
            int f  = tid + i * NTHREADS;
            int r  = f >> 5;
            int c4 = (f & 31) * 4;
            const float4 v = *(const float4*)(w2p + (size_t)(k0 + r) * DIM + c4);
            uint32_t* d1 = Bs + r * BPAD + c4;
            d1[0] = f2tf(v.x); d1[1] = f2tf(v.y); d1[2] = f2tf(v.z); d1[3] = f2tf(v.w);
        }
        __syncthreads();

#pragma unroll
        for (int kk = 0; kk < BK; kk += 8) {
            uint32_t a[2][4];
#pragma unroll
            for (int ms = 0; ms < 2; ms++) {
                int rb = mBase + ms * 16;
                a[ms][0] = As[(rb + gid    ) * APAD + kk + tig    ];
                a[ms][1] = As[(rb + gid + 8) * APAD + kk + tig    ];
                a[ms][2] = As[(rb + gid    ) * APAD + kk + tig + 4];
                a[ms][3] = As[(rb + gid + 8) * APAD + kk + tig + 4];
            }
#pragma unroll
            for (int ns = 0; ns < 4; ns++) {
                int ncol = nBase + ns * 8 + gid;
                uint32_t bf[2] = { Bs[(kk + tig) * BPAD + ncol], Bs[(kk + tig + 4) * BPAD + ncol] };
                mma8(c[0][ns], a[0], bf);
                mma8(c[1][ns], a[1], bf);
            }
        }
        __syncthreads();
    }

    // scaled scatter into per-slot buffers (each (slot, token) cell written once)
#pragma unroll
    for (int ms = 0; ms < 2; ms++) {
#pragma unroll
        for (int half = 0; half < 2; half++) {
            int grow = mt * BM + mBase + ms * 16 + gid + half * 8;
            if (grow < cnt) {
                int   gi = e * T_TOK + grow;
                int   t  = g_tok[gi];
                int   s  = g_slot[gi];
                float cf = g_coef[gi];
                float* op = g_out2 + ((size_t)s * T_TOK + t) * DIM + nt * BN + nBase;
#pragma unroll
                for (int ns = 0; ns < 4; ns++) {
                    int col = ns * 8 + tig * 2;
                    float2 o;
                    o.x = cf * c[ms][ns][half * 2 + 0];
                    o.y = cf * c[ms][ns][half * 2 + 1];
                    *(float2*)(op + col) = o;
                }
            }
        }
    }
}

// ---------------- kernel 4: combine slots -> output -------------------------
__global__ void k_combine(float* __restrict__ out) {
    size_t i = ((size_t)blockIdx.x * 256 + threadIdx.x) * 4;
    float4 a = *(const float4*)(g_out2 + i);
    float4 b = *(const float4*)(g_out2 + (size_t)T_TOK * DIM + i);
    float4 r;
    r.x = a.x + b.x; r.y = a.y + b.y; r.z = a.z + b.z; r.w = a.w + b.w;
    *(float4*)(out + i) = r;
}

// ---------------- launch -----------------------------------------------------
extern "C" void kernel_launch(void* const* d_in, const int* in_sizes, int n_in,
                              void* d_out, int out_size) {
    const float* x  = (const float*)d_in[0];
    const float* gw = (const float*)d_in[1];
    const float* w1 = (const float*)d_in[2];
    const float* w2 = (const float*)d_in[3];
    const float* w3 = (const float*)d_in[4];

    cudaFuncSetAttribute(k_gemm1, cudaFuncAttributeMaxDynamicSharedMemorySize, SMEM1_BYTES);

    k_zero<<<1, 32>>>();
    k_router<<<T_TOK / 8, 256>>>(x, gw);

    dim3 g1(MLPD / BN, T_TOK / BM, NEXP);          // (16, 64, 8)
    k_gemm1<<<g1, NTHREADS, SMEM1_BYTES>>>(x, w1, w3);

    dim3 g2(DIM / BN, T_TOK / BM, NEXP);           // (8, 64, 8)
    k_gemm2<<<g2, NTHREADS>>>(w2);

    k_combine<<<(T_TOK * DIM / 4) / 256, 256>>>((float*)d_out);
}

// round 9
// speedup vs baseline: 2.9545x; 2.1222x over previous
#include <cuda_runtime.h>
#include <cuda_fp16.h>
#include <cstdint>
#include <math.h>

#define T_TOK 8192
#define DIM   1024
#define MLPD  2048
#define NEXP  8

#define BM 128
#define BN 128
#define BK 32          // k halfs per stage

#define AP 20          // uint32 pitch per A row (16 data words + pad) -> conflict-free frags
#define BP 136         // uint32 pitch per B kp-row (128 data words + pad)

#define A_STG (BM * AP)          // 2560 words
#define B_STG ((BK / 2) * BP)    // 2176 words

#define NTHREADS 512

// gemm1 dynamic smem: A x2 stages, B1 x2, B3 x2, sTok
#define SM1_WORDS (2 * A_STG + 4 * B_STG + BM)
#define SMEM1_BYTES (SM1_WORDS * 4)     // 55808

// ---------------- scratch (static device globals; no allocation) ------------
__device__ int      g_count[NEXP];
__device__ int      g_tok [NEXP * T_TOK];
__device__ int      g_slot[NEXP * T_TOK];
__device__ float    g_coef[NEXP * T_TOK];
__device__ __half   g_xh  [(size_t)T_TOK * DIM];                 // x in fp16, row-major
__device__ __half   g_h   [(size_t)NEXP * T_TOK * MLPD];         // SwiGLU out, fp16
__device__ uint32_t g_w1h [(size_t)NEXP * (DIM / 2) * MLPD];     // packed {w[2kp][n], w[2kp+1][n]}
__device__ uint32_t g_w3h [(size_t)NEXP * (DIM / 2) * MLPD];
__device__ uint32_t g_w2h [(size_t)NEXP * (MLPD / 2) * DIM];
__device__ float    g_out2[2ull * T_TOK * DIM];

// ---------------- helpers ---------------------------------------------------
__device__ __forceinline__ uint32_t smem_u32(const void* p) {
    uint32_t a;
    asm("{ .reg .u64 t; cvta.to.shared.u64 t, %1; cvt.u32.u64 %0, t; }" : "=r"(a) : "l"(p));
    return a;
}

__device__ __forceinline__ void cpa16(uint32_t dst, const void* src) {
    asm volatile("cp.async.cg.shared.global [%0], [%1], 16;" :: "r"(dst), "l"(src) : "memory");
}
#define CP_COMMIT()  asm volatile("cp.async.commit_group;" ::: "memory")
#define CP_WAIT(n)   asm volatile("cp.async.wait_group %0;" :: "n"(n) : "memory")

__device__ __forceinline__ void mma16(float c[4], const uint32_t a[4], const uint32_t b[2]) {
    asm volatile(
        "mma.sync.aligned.m16n8k16.row.col.f32.f16.f16.f32 "
        "{%0,%1,%2,%3}, {%4,%5,%6,%7}, {%8,%9}, {%0,%1,%2,%3};"
        : "+f"(c[0]), "+f"(c[1]), "+f"(c[2]), "+f"(c[3])
        : "r"(a[0]), "r"(a[1]), "r"(a[2]), "r"(a[3]), "r"(b[0]), "r"(b[1]));
}

// ---------------- kernel 0: zero counters -----------------------------------
__global__ void k_zero() {
    if (threadIdx.x < NEXP) g_count[threadIdx.x] = 0;
}

// ---------------- kernel 1: router (one warp per token, fp32) ---------------
__global__ void k_router(const float* __restrict__ x, const float* __restrict__ gw) {
    int gtid = blockIdx.x * blockDim.x + threadIdx.x;
    int wid  = gtid >> 5;
    int lane = gtid & 31;
    if (wid >= T_TOK) return;

    const float* xr = x + (size_t)wid * DIM;
    float acc[8] = {0.f, 0.f, 0.f, 0.f, 0.f, 0.f, 0.f, 0.f};
    for (int d = lane; d < DIM; d += 32) {
        float xv = __ldg(xr + d);
        const float4 g0 = *(const float4*)(gw + d * 8);
        const float4 g1 = *(const float4*)(gw + d * 8 + 4);
        acc[0] += xv * g0.x; acc[1] += xv * g0.y; acc[2] += xv * g0.z; acc[3] += xv * g0.w;
        acc[4] += xv * g1.x; acc[5] += xv * g1.y; acc[6] += xv * g1.z; acc[7] += xv * g1.w;
    }
#pragma unroll
    for (int i = 0; i < 8; i++) {
#pragma unroll
        for (int o = 16; o; o >>= 1) acc[i] += __shfl_xor_sync(0xffffffffu, acc[i], o);
    }
    if (lane == 0) {
        int e0 = 0;
#pragma unroll
        for (int i = 1; i < 8; i++) if (acc[i] > acc[e0]) e0 = i;
        int e1 = -1;
#pragma unroll
        for (int i = 0; i < 8; i++) {
            if (i == e0) continue;
            if (e1 < 0 || acc[i] > acc[e1]) e1 = i;
        }
        float m  = acc[e0];
        float p0 = expf(acc[e0] - m);
        float p1 = expf(acc[e1] - m);
        float s  = p0 + p1;

        int pos0 = atomicAdd(&g_count[e0], 1);
        g_tok [e0 * T_TOK + pos0] = wid;
        g_slot[e0 * T_TOK + pos0] = 0;
        g_coef[e0 * T_TOK + pos0] = p0 / s;
        int pos1 = atomicAdd(&g_count[e1], 1);
        g_tok [e1 * T_TOK + pos1] = wid;
        g_slot[e1 * T_TOK + pos1] = 1;
        g_coef[e1 * T_TOK + pos1] = p1 / s;
    }
}

// ---------------- kernel 1b: x -> fp16 --------------------------------------
__global__ void k_cvt_x(const float* __restrict__ x) {
    size_t i = ((size_t)blockIdx.x * 256 + threadIdx.x) * 2;
    float2 v = *(const float2*)(x + i);
    *(__half2*)(g_xh + i) = __floats2half2_rn(v.x, v.y);
}

// ---------------- kernel 1c: pack weights into k-pair fp16 words ------------
// src [e][R][C] fp32 -> dst [e][R/2][C] words, word = {h(src[2kp][n]), h(src[2kp+1][n])}
__global__ void k_pack(const float* __restrict__ src, uint32_t* __restrict__ dst,
                       int R, int C) {
    int e  = blockIdx.z;
    int kp = blockIdx.y;
    int n  = blockIdx.x * 256 + threadIdx.x;
    float f0 = src[((size_t)e * R + 2 * kp    ) * C + n];
    float f1 = src[((size_t)e * R + 2 * kp + 1) * C + n];
    __half2 h = __floats2half2_rn(f0, f1);
    dst[((size_t)e * (R / 2) + kp) * C + n] = *(uint32_t*)&h;
}

// ---------------- kernel 2: GEMM1 (x·w1, x·w3) + SwiGLU, fp16 + cp.async ----
// grid (MLPD/BN, T_TOK/BM, NEXP), 512 threads = 16 warps (4M x 4N), warp tile 32x32
__global__ __launch_bounds__(NTHREADS, 1)
void k_gemm1() {
    int e   = blockIdx.z;
    int cnt = g_count[e];
    int mt  = blockIdx.y;
    if (mt * BM >= cnt) return;
    int nt  = blockIdx.x;

    extern __shared__ uint32_t sm[];
    uint32_t* Abuf = sm;                       // 2 stages
    uint32_t* B1b  = sm + 2 * A_STG;
    uint32_t* B3b  = sm + 2 * A_STG + 2 * B_STG;
    int*      sTok = (int*)(sm + 2 * A_STG + 4 * B_STG);

    int tid    = threadIdx.x;
    int warpId = tid >> 5;
    int lane   = tid & 31;
    int gid    = lane >> 2;
    int tig    = lane & 3;
    int mBase  = (warpId & 3) * 32;
    int nBase  = (warpId >> 2) * 32;

    if (tid < BM) {
        int r = mt * BM + tid;
        sTok[tid] = (r < cnt) ? g_tok[e * T_TOK + r] : g_tok[e * T_TOK];
    }
    __syncthreads();

    uint32_t smB = smem_u32(sm);

    // per-thread loader coordinates (fixed across stages)
    int lr  = tid >> 2, lwg = tid & 3;           // A: row, 16B-group
    int lkp = tid >> 5, lng = tid & 31;          // B: kp row, 16B-group
    const __half*   srcA  = g_xh + (size_t)sTok[lr] * DIM + lwg * 8;
    const uint32_t* srcB1 = g_w1h + ((size_t)e * (DIM / 2) + lkp) * MLPD + nt * BN + lng * 4;
    const uint32_t* srcB3 = g_w3h + ((size_t)e * (DIM / 2) + lkp) * MLPD + nt * BN + lng * 4;
    uint32_t dA  = smB + (lr * AP + lwg * 4) * 4;
    uint32_t dB1 = smB + (2 * A_STG + lkp * BP + lng * 4) * 4;
    uint32_t dB3 = smB + (2 * A_STG + 2 * B_STG + lkp * BP + lng * 4) * 4;

    float c1[2][4][4], c3[2][4][4];
#pragma unroll
    for (int a = 0; a < 2; a++)
#pragma unroll
        for (int b = 0; b < 4; b++)
#pragma unroll
            for (int d = 0; d < 4; d++) { c1[a][b][d] = 0.f; c3[a][b][d] = 0.f; }

    const int NS = DIM / BK;   // 32
    // prologue: stage 0 into buffer 0
    cpa16(dA, srcA);
    cpa16(dB1, srcB1);
    cpa16(dB3, srcB3);
    CP_COMMIT();

    for (int s = 0; s < NS; s++) {
        int buf = s & 1;
        if (s + 1 < NS) {
            int nb = (s + 1) & 1;
            cpa16(dA  + nb * A_STG * 4, srcA  + (s + 1) * BK);
            cpa16(dB1 + nb * B_STG * 4, srcB1 + (size_t)(s + 1) * (BK / 2) * MLPD);
            cpa16(dB3 + nb * B_STG * 4, srcB3 + (size_t)(s + 1) * (BK / 2) * MLPD);
            CP_COMMIT();
            CP_WAIT(1);
        } else {
            CP_WAIT(0);
        }
        __syncthreads();

        const uint32_t* A  = Abuf + buf * A_STG;
        const uint32_t* B1 = B1b  + buf * B_STG;
        const uint32_t* B3 = B3b  + buf * B_STG;
#pragma unroll
        for (int kk = 0; kk < 2; kk++) {      // two k16 chunks per stage
            int kp8 = kk * 8;
            uint32_t a[2][4];
#pragma unroll
            for (int ms = 0; ms < 2; ms++) {
                int rb = mBase + ms * 16;
                a[ms][0] = A[(rb + gid    ) * AP + kp8 + tig    ];
                a[ms][1] = A[(rb + gid + 8) * AP + kp8 + tig    ];
                a[ms][2] = A[(rb + gid    ) * AP + kp8 + tig + 4];
                a[ms][3] = A[(rb + gid + 8) * AP + kp8 + tig + 4];
            }
#pragma unroll
            for (int ns = 0; ns < 4; ns++) {
                int ncol = nBase + ns * 8 + gid;
                uint32_t b1f[2] = { B1[(kp8 + tig) * BP + ncol], B1[(kp8 + tig + 4) * BP + ncol] };
                uint32_t b3f[2] = { B3[(kp8 + tig) * BP + ncol], B3[(kp8 + tig + 4) * BP + ncol] };
                mma16(c1[0][ns], a[0], b1f);
                mma16(c1[1][ns], a[1], b1f);
                mma16(c3[0][ns], a[0], b3f);
                mma16(c3[1][ns], a[1], b3f);
            }
        }
        __syncthreads();
    }

    // SwiGLU epilogue -> g_h (fp16)
#pragma unroll
    for (int ms = 0; ms < 2; ms++) {
#pragma unroll
        for (int half = 0; half < 2; half++) {
            int grow = mt * BM + mBase + ms * 16 + gid + half * 8;
            if (grow < cnt) {
                size_t rowoff = ((size_t)e * T_TOK + grow) * MLPD;
#pragma unroll
                for (int ns = 0; ns < 4; ns++) {
                    int col = nt * BN + nBase + ns * 8 + tig * 2;
                    float v1a = c1[ms][ns][half * 2 + 0];
                    float v1b = c1[ms][ns][half * 2 + 1];
                    float v3a = c3[ms][ns][half * 2 + 0];
                    float v3b = c3[ms][ns][half * 2 + 1];
                    float ox = v1a / (1.f + expf(-v1a)) * v3a;
                    float oy = v1b / (1.f + expf(-v1b)) * v3b;
                    *(__half2*)(g_h + rowoff + col) = __floats2half2_rn(ox, oy);
                }
            }
        }
    }
}

// ---------------- kernel 3: GEMM2 (h·w2, scaled scatter), fp16 + cp.async ---
// grid (DIM/BN, T_TOK/BM, NEXP), 512 threads
__global__ __launch_bounds__(NTHREADS, 1)
void k_gemm2() {
    int e   = blockIdx.z;
    int cnt = g_count[e];
    int mt  = blockIdx.y;
    if (mt * BM >= cnt) return;
    int nt  = blockIdx.x;

    __shared__ uint32_t sm[2 * A_STG + 2 * B_STG];
    uint32_t* Abuf = sm;
    uint32_t* Bb   = sm + 2 * A_STG;

    int tid    = threadIdx.x;
    int warpId = tid >> 5;
    int lane   = tid & 31;
    int gid    = lane >> 2;
    int tig    = lane & 3;
    int mBase  = (warpId & 3) * 32;
    int nBase  = (warpId >> 2) * 32;

    uint32_t smB = smem_u32(sm);
    int lr  = tid >> 2, lwg = tid & 3;
    int lkp = tid >> 5, lng = tid & 31;
    // rows >= cnt read stale-but-finite h scratch; results discarded.
    const __half*   srcA = g_h + ((size_t)e * T_TOK + (size_t)mt * BM + lr) * MLPD + lwg * 8;
    const uint32_t* srcB = g_w2h + ((size_t)e * (MLPD / 2) + lkp) * DIM + nt * BN + lng * 4;
    uint32_t dA = smB + (lr * AP + lwg * 4) * 4;
    uint32_t dB = smB + (2 * A_STG + lkp * BP + lng * 4) * 4;

    float c[2][4][4];
#pragma unroll
    for (int a = 0; a < 2; a++)
#pragma unroll
        for (int b = 0; b < 4; b++)
#pragma unroll
            for (int d = 0; d < 4; d++) c[a][b][d] = 0.f;

    const int NS = MLPD / BK;  // 64
    cpa16(dA, srcA);
    cpa16(dB, srcB);
    CP_COMMIT();

    for (int s = 0; s < NS; s++) {
        int buf = s & 1;
        if (s + 1 < NS) {
            int nb = (s + 1) & 1;
            cpa16(dA + nb * A_STG * 4, srcA + (s + 1) * BK);
            cpa16(dB + nb * B_STG * 4, srcB + (size_t)(s + 1) * (BK / 2) * DIM);
            CP_COMMIT();
            CP_WAIT(1);
        } else {
            CP_WAIT(0);
        }
        __syncthreads();

        const uint32_t* A = Abuf + buf * A_STG;
        const uint32_t* B = Bb   + buf * B_STG;
#pragma unroll
        for (int kk = 0; kk < 2; kk++) {
            int kp8 = kk * 8;
            uint32_t a[2][4];
#pragma unroll
            for (int ms = 0; ms < 2; ms++) {
                int rb = mBase + ms * 16;
                a[ms][0] = A[(rb + gid    ) * AP + kp8 + tig    ];
                a[ms][1] = A[(rb + gid + 8) * AP + kp8 + tig    ];
                a[ms][2] = A[(rb + gid    ) * AP + kp8 + tig + 4];
                a[ms][3] = A[(rb + gid + 8) * AP + kp8 + tig + 4];
            }
#pragma unroll
            for (int ns = 0; ns < 4; ns++) {
                int ncol = nBase + ns * 8 + gid;
                uint32_t bf[2] = { B[(kp8 + tig) * BP + ncol], B[(kp8 + tig + 4) * BP + ncol] };
                mma16(c[0][ns], a[0], bf);
                mma16(c[1][ns], a[1], bf);
            }
        }
        __syncthreads();
    }

    // scaled scatter into per-slot buffers (each (slot, token) cell written once)
#pragma unroll
    for (int ms = 0; ms < 2; ms++) {
#pragma unroll
        for (int half = 0; half < 2; half++) {
            int grow = mt * BM + mBase + ms * 16 + gid + half * 8;
            if (grow < cnt) {
                int   gi = e * T_TOK + grow;
                int   t  = g_tok[gi];
                int   sl = g_slot[gi];
                float cf = g_coef[gi];
                float* op = g_out2 + ((size_t)sl * T_TOK + t) * DIM + nt * BN + nBase;
#pragma unroll
                for (int ns = 0; ns < 4; ns++) {
                    int col = ns * 8 + tig * 2;
                    float2 o;
                    o.x = cf * c[ms][ns][half * 2 + 0];
                    o.y = cf * c[ms][ns][half * 2 + 1];
                    *(float2*)(op + col) = o;
                }
            }
        }
    }
}

// ---------------- kernel 4: combine slots -> output -------------------------
__global__ void k_combine(float* __restrict__ out) {
    size_t i = ((size_t)blockIdx.x * 256 + threadIdx.x) * 4;
    float4 a = *(const float4*)(g_out2 + i);
    float4 b = *(const float4*)(g_out2 + (size_t)T_TOK * DIM + i);
    float4 r;
    r.x = a.x + b.x; r.y = a.y + b.y; r.z = a.z + b.z; r.w = a.w + b.w;
    *(float4*)(out + i) = r;
}

// ---------------- launch -----------------------------------------------------
extern "C" void kernel_launch(void* const* d_in, const int* in_sizes, int n_in,
                              void* d_out, int out_size) {
    const float* x  = (const float*)d_in[0];
    const float* gw = (const float*)d_in[1];
    const float* w1 = (const float*)d_in[2];
    const float* w2 = (const float*)d_in[3];
    const float* w3 = (const float*)d_in[4];

    cudaFuncSetAttribute(k_gemm1, cudaFuncAttributeMaxDynamicSharedMemorySize, SMEM1_BYTES);

    k_zero<<<1, 32>>>();
    k_router<<<T_TOK / 8, 256>>>(x, gw);

    k_cvt_x<<<(T_TOK * DIM / 2) / 256, 256>>>(x);
    uint32_t* w1h; cudaGetSymbolAddress((void**)&w1h, g_w1h);
    uint32_t* w3h; cudaGetSymbolAddress((void**)&w3h, g_w3h);
    uint32_t* w2h; cudaGetSymbolAddress((void**)&w2h, g_w2h);
    k_pack<<<dim3(MLPD / 256, DIM / 2, NEXP), 256>>>(w1, w1h, DIM, MLPD);
    k_pack<<<dim3(MLPD / 256, DIM / 2, NEXP), 256>>>(w3, w3h, DIM, MLPD);
    k_pack<<<dim3(DIM / 256, MLPD / 2, NEXP), 256>>>(w2, w2h, MLPD, DIM);

    k_gemm1<<<dim3(MLPD / BN, T_TOK / BM, NEXP), NTHREADS, SMEM1_BYTES>>>();
    k_gemm2<<<dim3(DIM / BN, T_TOK / BM, NEXP), NTHREADS>>>();

    k_combine<<<(T_TOK * DIM / 4) / 256, 256>>>((float*)d_out);
}

// round 10
// speedup vs baseline: 3.3630x; 1.1383x over previous
#include <cuda_runtime.h>
#include <cuda_fp16.h>
#include <cstdint>
#include <math.h>

#define T_TOK 8192
#define DIM   1024
#define MLPD  2048
#define NEXP  8

#define BM 128
#define BN 128
#define BK 32          // k halfs per stage

#define AP 20          // uint32 pitch per A row (16 data words + pad) -> conflict-free frags
#define BP 136         // uint32 pitch per B kp-row (128 data words + pad)

#define A_STG (BM * AP)          // 2560 words
#define B_STG ((BK / 2) * BP)    // 2176 words

#define NTHREADS 512
#define NSTAGE 3

// gemm1 dynamic smem: A x3 stages, B1 x3, B3 x3, sTok
#define SM1_WORDS (NSTAGE * A_STG + 2 * NSTAGE * B_STG + BM)
#define SMEM1_BYTES (SM1_WORDS * 4)                       // 83456
// gemm2 dynamic smem: A x3, B x3
#define SM2_WORDS (NSTAGE * (A_STG + B_STG))
#define SMEM2_BYTES (SM2_WORDS * 4)                       // 56832

// ---------------- scratch (static device globals; no allocation) ------------
__device__ int      g_count[NEXP];
__device__ int      g_tok [NEXP * T_TOK];
__device__ int      g_slot[NEXP * T_TOK];
__device__ float    g_coef[NEXP * T_TOK];
__device__ __half   g_xh  [(size_t)T_TOK * DIM];                 // x in fp16, row-major
__device__ __half   g_h   [(size_t)NEXP * T_TOK * MLPD];         // SwiGLU out, fp16
__device__ uint32_t g_w1h [(size_t)NEXP * (DIM / 2) * MLPD];     // packed {w[2kp][n], w[2kp+1][n]}
__device__ uint32_t g_w3h [(size_t)NEXP * (DIM / 2) * MLPD];
__device__ uint32_t g_w2h [(size_t)NEXP * (MLPD / 2) * DIM];
__device__ float    g_out2[2ull * T_TOK * DIM];

// ---------------- helpers ---------------------------------------------------
__device__ __forceinline__ uint32_t smem_u32(const void* p) {
    uint32_t a;
    asm("{ .reg .u64 t; cvta.to.shared.u64 t, %1; cvt.u32.u64 %0, t; }" : "=r"(a) : "l"(p));
    return a;
}

__device__ __forceinline__ void cpa16(uint32_t dst, const void* src) {
    asm volatile("cp.async.cg.shared.global [%0], [%1], 16;" :: "r"(dst), "l"(src) : "memory");
}
#define CP_COMMIT()  asm volatile("cp.async.commit_group;" ::: "memory")
#define CP_WAIT(n)   asm volatile("cp.async.wait_group %0;" :: "n"(n) : "memory")

__device__ __forceinline__ void mma16(float c[4], const uint32_t a[4], const uint32_t b[2]) {
    asm volatile(
        "mma.sync.aligned.m16n8k16.row.col.f32.f16.f16.f32 "
        "{%0,%1,%2,%3}, {%4,%5,%6,%7}, {%8,%9}, {%0,%1,%2,%3};"
        : "+f"(c[0]), "+f"(c[1]), "+f"(c[2]), "+f"(c[3])
        : "r"(a[0]), "r"(a[1]), "r"(a[2]), "r"(a[3]), "r"(b[0]), "r"(b[1]));
}

// ---------------- kernel 0: zero counters -----------------------------------
__global__ void k_zero() {
    if (threadIdx.x < NEXP) g_count[threadIdx.x] = 0;
}

// ---------------- kernel 1: router (one warp per token, fp32) ---------------
__global__ void k_router(const float* __restrict__ x, const float* __restrict__ gw) {
    int gtid = blockIdx.x * blockDim.x + threadIdx.x;
    int wid  = gtid >> 5;
    int lane = gtid & 31;
    if (wid >= T_TOK) return;

    const float* xr = x + (size_t)wid * DIM;
    float acc[8] = {0.f, 0.f, 0.f, 0.f, 0.f, 0.f, 0.f, 0.f};
    for (int d = lane; d < DIM; d += 32) {
        float xv = __ldg(xr + d);
        const float4 g0 = *(const float4*)(gw + d * 8);
        const float4 g1 = *(const float4*)(gw + d * 8 + 4);
        acc[0] += xv * g0.x; acc[1] += xv * g0.y; acc[2] += xv * g0.z; acc[3] += xv * g0.w;
        acc[4] += xv * g1.x; acc[5] += xv * g1.y; acc[6] += xv * g1.z; acc[7] += xv * g1.w;
    }
#pragma unroll
    for (int i = 0; i < 8; i++) {
#pragma unroll
        for (int o = 16; o; o >>= 1) acc[i] += __shfl_xor_sync(0xffffffffu, acc[i], o);
    }
    if (lane == 0) {
        int e0 = 0;
#pragma unroll
        for (int i = 1; i < 8; i++) if (acc[i] > acc[e0]) e0 = i;
        int e1 = -1;
#pragma unroll
        for (int i = 0; i < 8; i++) {
            if (i == e0) continue;
            if (e1 < 0 || acc[i] > acc[e1]) e1 = i;
        }
        float m  = acc[e0];
        float p0 = expf(acc[e0] - m);
        float p1 = expf(acc[e1] - m);
        float s  = p0 + p1;

        int pos0 = atomicAdd(&g_count[e0], 1);
        g_tok [e0 * T_TOK + pos0] = wid;
        g_slot[e0 * T_TOK + pos0] = 0;
        g_coef[e0 * T_TOK + pos0] = p0 / s;
        int pos1 = atomicAdd(&g_count[e1], 1);
        g_tok [e1 * T_TOK + pos1] = wid;
        g_slot[e1 * T_TOK + pos1] = 1;
        g_coef[e1 * T_TOK + pos1] = p1 / s;
    }
}

// ---------------- kernel 1b: x -> fp16 --------------------------------------
__global__ void k_cvt_x(const float* __restrict__ x) {
    size_t i = ((size_t)blockIdx.x * 256 + threadIdx.x) * 4;
    float4 v = *(const float4*)(x + i);
    __half2 h0 = __floats2half2_rn(v.x, v.y);
    __half2 h1 = __floats2half2_rn(v.z, v.w);
    uint2 o = { *(uint32_t*)&h0, *(uint32_t*)&h1 };
    *(uint2*)(g_xh + i) = o;
}

// ---------------- kernel 1c: pack weights into k-pair fp16 words ------------
// src [e][R][C] fp32 -> dst [e][R/2][C] words, word = {h(src[2kp][n]), h(src[2kp+1][n])}
// grid (C/1024, R/2, E), 256 threads, 4 cols/thread
__global__ void k_pack(const float* __restrict__ src, uint32_t* __restrict__ dst,
                       int R, int C) {
    int e  = blockIdx.z;
    int kp = blockIdx.y;
    int n  = (blockIdx.x * 256 + threadIdx.x) * 4;
    const float4 a = *(const float4*)(src + ((size_t)e * R + 2 * kp    ) * C + n);
    const float4 b = *(const float4*)(src + ((size_t)e * R + 2 * kp + 1) * C + n);
    __half2 h0 = __floats2half2_rn(a.x, b.x);
    __half2 h1 = __floats2half2_rn(a.y, b.y);
    __half2 h2 = __floats2half2_rn(a.z, b.z);
    __half2 h3 = __floats2half2_rn(a.w, b.w);
    uint4 o = { *(uint32_t*)&h0, *(uint32_t*)&h1, *(uint32_t*)&h2, *(uint32_t*)&h3 };
    *(uint4*)(dst + ((size_t)e * (R / 2) + kp) * C + n) = o;
}

// ---------------- kernel 2: GEMM1 (x·w1, x·w3) + SwiGLU ---------------------
// grid (MLPD/BN, T_TOK/BM, NEXP), 512 threads = 16 warps (4M x 4N), warp tile 32x32
// 3-stage cp.async pipeline, one barrier per k-iter.
__global__ __launch_bounds__(NTHREADS, 1)
void k_gemm1() {
    int e   = blockIdx.z;
    int cnt = g_count[e];
    int mt  = blockIdx.y;
    if (mt * BM >= cnt) return;
    int nt  = blockIdx.x;

    extern __shared__ uint32_t sm[];
    uint32_t* Abuf = sm;                                   // 3 stages
    uint32_t* B1b  = sm + NSTAGE * A_STG;
    uint32_t* B3b  = sm + NSTAGE * A_STG + NSTAGE * B_STG;
    int*      sTok = (int*)(sm + NSTAGE * A_STG + 2 * NSTAGE * B_STG);

    int tid    = threadIdx.x;
    int warpId = tid >> 5;
    int lane   = tid & 31;
    int gid    = lane >> 2;
    int tig    = lane & 3;
    int mBase  = (warpId & 3) * 32;
    int nBase  = (warpId >> 2) * 32;

    if (tid < BM) {
        int r = mt * BM + tid;
        sTok[tid] = (r < cnt) ? g_tok[e * T_TOK + r] : g_tok[e * T_TOK];
    }
    __syncthreads();

    uint32_t smB = smem_u32(sm);
    int lr  = tid >> 2, lwg = tid & 3;           // A: row, 16B-group
    int lkp = tid >> 5, lng = tid & 31;          // B: kp row, 16B-group
    const __half*   srcA  = g_xh + (size_t)sTok[lr] * DIM + lwg * 8;
    const uint32_t* srcB1 = g_w1h + ((size_t)e * (DIM / 2) + lkp) * MLPD + nt * BN + lng * 4;
    const uint32_t* srcB3 = g_w3h + ((size_t)e * (DIM / 2) + lkp) * MLPD + nt * BN + lng * 4;
    uint32_t dA  = smB + (lr * AP + lwg * 4) * 4;
    uint32_t dB1 = smB + (NSTAGE * A_STG + lkp * BP + lng * 4) * 4;
    uint32_t dB3 = smB + (NSTAGE * A_STG + NSTAGE * B_STG + lkp * BP + lng * 4) * 4;

    auto issue = [&](int s, int buf) {
        cpa16(dA  + buf * A_STG * 4, srcA  + s * BK);
        cpa16(dB1 + buf * B_STG * 4, srcB1 + (size_t)s * (BK / 2) * MLPD);
        cpa16(dB3 + buf * B_STG * 4, srcB3 + (size_t)s * (BK / 2) * MLPD);
        CP_COMMIT();
    };

    float c1[2][4][4], c3[2][4][4];
#pragma unroll
    for (int a = 0; a < 2; a++)
#pragma unroll
        for (int b = 0; b < 4; b++)
#pragma unroll
            for (int d = 0; d < 4; d++) { c1[a][b][d] = 0.f; c3[a][b][d] = 0.f; }

    const int NS = DIM / BK;   // 32
    issue(0, 0);
    issue(1, 1);

    int buf = 0;
    for (int s = 0; s < NS; s++) {
        if (s == NS - 1) { CP_WAIT(0); } else { CP_WAIT(1); }
        __syncthreads();
        if (s + 2 < NS) {
            int nb = buf + 2; if (nb >= NSTAGE) nb -= NSTAGE;
            issue(s + 2, nb);
        }

        const uint32_t* A  = Abuf + buf * A_STG;
        const uint32_t* B1 = B1b  + buf * B_STG;
        const uint32_t* B3 = B3b  + buf * B_STG;
#pragma unroll
        for (int kk = 0; kk < 2; kk++) {      // two k16 chunks per stage
            int kp8 = kk * 8;
            uint32_t a[2][4];
#pragma unroll
            for (int ms = 0; ms < 2; ms++) {
                int rb = mBase + ms * 16;
                a[ms][0] = A[(rb + gid    ) * AP + kp8 + tig    ];
                a[ms][1] = A[(rb + gid + 8) * AP + kp8 + tig    ];
                a[ms][2] = A[(rb + gid    ) * AP + kp8 + tig + 4];
                a[ms][3] = A[(rb + gid + 8) * AP + kp8 + tig + 4];
            }
#pragma unroll
            for (int ns = 0; ns < 4; ns++) {
                int ncol = nBase + ns * 8 + gid;
                uint32_t b1f[2] = { B1[(kp8 + tig) * BP + ncol], B1[(kp8 + tig + 4) * BP + ncol] };
                uint32_t b3f[2] = { B3[(kp8 + tig) * BP + ncol], B3[(kp8 + tig + 4) * BP + ncol] };
                mma16(c1[0][ns], a[0], b1f);
                mma16(c1[1][ns], a[1], b1f);
                mma16(c3[0][ns], a[0], b3f);
                mma16(c3[1][ns], a[1], b3f);
            }
        }
        if (++buf >= NSTAGE) buf = 0;
    }

    // SwiGLU epilogue -> g_h (fp16)
#pragma unroll
    for (int ms = 0; ms < 2; ms++) {
#pragma unroll
        for (int half = 0; half < 2; half++) {
            int grow = mt * BM + mBase + ms * 16 + gid + half * 8;
            if (grow < cnt) {
                size_t rowoff = ((size_t)e * T_TOK + grow) * MLPD;
#pragma unroll
                for (int ns = 0; ns < 4; ns++) {
                    int col = nt * BN + nBase + ns * 8 + tig * 2;
                    float v1a = c1[ms][ns][half * 2 + 0];
                    float v1b = c1[ms][ns][half * 2 + 1];
                    float v3a = c3[ms][ns][half * 2 + 0];
                    float v3b = c3[ms][ns][half * 2 + 1];
                    float ox = v1a / (1.f + __expf(-v1a)) * v3a;
                    float oy = v1b / (1.f + __expf(-v1b)) * v3b;
                    *(__half2*)(g_h + rowoff + col) = __floats2half2_rn(ox, oy);
                }
            }
        }
    }
}

// ---------------- kernel 3: GEMM2 (h·w2, scaled scatter) --------------------
// grid (DIM/BN, T_TOK/BM, NEXP), 512 threads, 2 CTAs/SM, 3-stage pipeline
__global__ __launch_bounds__(NTHREADS, 2)
void k_gemm2() {
    int e   = blockIdx.z;
    int cnt = g_count[e];
    int mt  = blockIdx.y;
    if (mt * BM >= cnt) return;
    int nt  = blockIdx.x;

    extern __shared__ uint32_t sm[];
    uint32_t* Abuf = sm;
    uint32_t* Bb   = sm + NSTAGE * A_STG;

    int tid    = threadIdx.x;
    int warpId = tid >> 5;
    int lane   = tid & 31;
    int gid    = lane >> 2;
    int tig    = lane & 3;
    int mBase  = (warpId & 3) * 32;
    int nBase  = (warpId >> 2) * 32;

    uint32_t smB = smem_u32(sm);
    int lr  = tid >> 2, lwg = tid & 3;
    int lkp = tid >> 5, lng = tid & 31;
    // rows >= cnt read stale-but-finite h scratch; results discarded.
    const __half*   srcA = g_h + ((size_t)e * T_TOK + (size_t)mt * BM + lr) * MLPD + lwg * 8;
    const uint32_t* srcB = g_w2h + ((size_t)e * (MLPD / 2) + lkp) * DIM + nt * BN + lng * 4;
    uint32_t dA = smB + (lr * AP + lwg * 4) * 4;
    uint32_t dB = smB + (NSTAGE * A_STG + lkp * BP + lng * 4) * 4;

    auto issue = [&](int s, int buf) {
        cpa16(dA + buf * A_STG * 4, srcA + s * BK);
        cpa16(dB + buf * B_STG * 4, srcB + (size_t)s * (BK / 2) * DIM);
        CP_COMMIT();
    };

    float c[2][4][4];
#pragma unroll
    for (int a = 0; a < 2; a++)
#pragma unroll
        for (int b = 0; b < 4; b++)
#pragma unroll
            for (int d = 0; d < 4; d++) c[a][b][d] = 0.f;

    const int NS = MLPD / BK;  // 64
    issue(0, 0);
    issue(1, 1);

    int buf = 0;
    for (int s = 0; s < NS; s++) {
        if (s == NS - 1) { CP_WAIT(0); } else { CP_WAIT(1); }
        __syncthreads();
        if (s + 2 < NS) {
            int nb = buf + 2; if (nb >= NSTAGE) nb -= NSTAGE;
            issue(s + 2, nb);
        }

        const uint32_t* A = Abuf + buf * A_STG;
        const uint32_t* B = Bb   + buf * B_STG;
#pragma unroll
        for (int kk = 0; kk < 2; kk++) {
            int kp8 = kk * 8;
            uint32_t a[2][4];
#pragma unroll
            for (int ms = 0; ms < 2; ms++) {
                int rb = mBase + ms * 16;
                a[ms][0] = A[(rb + gid    ) * AP + kp8 + tig    ];
                a[ms][1] = A[(rb + gid + 8) * AP + kp8 + tig    ];
                a[ms][2] = A[(rb + gid    ) * AP + kp8 + tig + 4];
                a[ms][3] = A[(rb + gid + 8) * AP + kp8 + tig + 4];
            }
#pragma unroll
            for (int ns = 0; ns < 4; ns++) {
                int ncol = nBase + ns * 8 + gid;
                uint32_t bf[2] = { B[(kp8 + tig) * BP + ncol], B[(kp8 + tig + 4) * BP + ncol] };
                mma16(c[0][ns], a[0], bf);
                mma16(c[1][ns], a[1], bf);
            }
        }
        if (++buf >= NSTAGE) buf = 0;
    }

    // scaled scatter into per-slot buffers (each (slot, token) cell written once)
#pragma unroll
    for (int ms = 0; ms < 2; ms++) {
#pragma unroll
        for (int half = 0; half < 2; half++) {
            int grow = mt * BM + mBase + ms * 16 + gid + half * 8;
            if (grow < cnt) {
                int   gi = e * T_TOK + grow;
                int   t  = g_tok[gi];
                int   sl = g_slot[gi];
                float cf = g_coef[gi];
                float* op = g_out2 + ((size_t)sl * T_TOK + t) * DIM + nt * BN + nBase;
#pragma unroll
                for (int ns = 0; ns < 4; ns++) {
                    int col = ns * 8 + tig * 2;
                    float2 o;
                    o.x = cf * c[ms][ns][half * 2 + 0];
                    o.y = cf * c[ms][ns][half * 2 + 1];
                    *(float2*)(op + col) = o;
                }
            }
        }
    }
}

// ---------------- kernel 4: combine slots -> output -------------------------
__global__ void k_combine(float* __restrict__ out) {
    size_t i = ((size_t)blockIdx.x * 256 + threadIdx.x) * 4;
    float4 a = *(const float4*)(g_out2 + i);
    float4 b = *(const float4*)(g_out2 + (size_t)T_TOK * DIM + i);
    float4 r;
    r.x = a.x + b.x; r.y = a.y + b.y; r.z = a.z + b.z; r.w = a.w + b.w;
    *(float4*)(out + i) = r;
}

// ---------------- launch -----------------------------------------------------
extern "C" void kernel_launch(void* const* d_in, const int* in_sizes, int n_in,
                              void* d_out, int out_size) {
    const float* x  = (const float*)d_in[0];
    const float* gw = (const float*)d_in[1];
    const float* w1 = (const float*)d_in[2];
    const float* w2 = (const float*)d_in[3];
    const float* w3 = (const float*)d_in[4];

    cudaFuncSetAttribute(k_gemm1, cudaFuncAttributeMaxDynamicSharedMemorySize, SMEM1_BYTES);
    cudaFuncSetAttribute(k_gemm2, cudaFuncAttributeMaxDynamicSharedMemorySize, SMEM2_BYTES);

    k_zero<<<1, 32>>>();
    k_router<<<T_TOK / 8, 256>>>(x, gw);

    k_cvt_x<<<(T_TOK * DIM / 4) / 256, 256>>>(x);
    uint32_t* w1h; cudaGetSymbolAddress((void**)&w1h, g_w1h);
    uint32_t* w3h; cudaGetSymbolAddress((void**)&w3h, g_w3h);
    uint32_t* w2h; cudaGetSymbolAddress((void**)&w2h, g_w2h);
    k_pack<<<dim3(MLPD / 1024, DIM / 2, NEXP), 256>>>(w1, w1h, DIM, MLPD);
    k_pack<<<dim3(MLPD / 1024, DIM / 2, NEXP), 256>>>(w3, w3h, DIM, MLPD);
    k_pack<<<dim3(DIM / 1024, MLPD / 2, NEXP), 256>>>(w2, w2h, MLPD, DIM);

    k_gemm1<<<dim3(MLPD / BN, T_TOK / BM, NEXP), NTHREADS, SMEM1_BYTES>>>();
    k_gemm2<<<dim3(DIM / BN, T_TOK / BM, NEXP), NTHREADS, SMEM2_BYTES>>>();

    k_combine<<<(T_TOK * DIM / 4) / 256, 256>>>((float*)d_out);
}